// round 1
// baseline (speedup 1.0000x reference)
#include <cuda_runtime.h>
#include <math.h>
#include <stdint.h>

// Problem dims (fixed by setup_inputs)
#define BQ 128      // batch
#define KQ 128      // num objects
#define VDQ 128     // vote feature dim
#define ODQ 256     // ref obj feature dim
#define EQ 300      // embedding dim
#define AQ 512      // attention dim
#define DQ 512      // hidden dim
#define VQ 4000     // vocab
#define TQ 32       // timesteps
#define XDIM 684    // E + VD + OD

// ------------------------- scratch (device globals) -------------------------
__device__ float g_att1[(size_t)BQ * KQ * AQ];      // 32 MB
__device__ float g_att2[BQ * AQ];
__device__ float g_gate[BQ * VDQ];
__device__ float g_h[BQ * DQ];
__device__ float g_c[BQ * DQ];
__device__ float g_x[BQ * XDIM];
__device__ float g_gates[BQ * 4 * DQ];
__device__ float g_init[BQ * (VDQ + ODQ)];
__device__ float g_predsT[(size_t)TQ * BQ * VQ];    // 64 MB, [t][b][v]
__device__ unsigned char g_mask[BQ * KQ];

__device__ __forceinline__ float sigf(float x) { return 1.f / (1.f + expf(-x)); }

// ------------------------- object mask kernel -------------------------------
__global__ void mask_kernel(const float* __restrict__ obj,
                            const float* __restrict__ center,
                            const float* __restrict__ xyz,
                            float* __restrict__ out_mask)
{
    int b = blockIdx.x, k = threadIdx.x;
    const float INF = __int_as_float(0x7f800000);

    float s0 = obj[(b * KQ + k) * 2];
    float s1 = obj[(b * KQ + k) * 2 + 1];
    float objn = 1.f / (1.f + expf(s0 - s1));   // softmax(...)[...,1]
    bool om = objn > 0.75f;

    float dx = center[b * 3 + 0] - xyz[(b * KQ + k) * 3 + 0];
    float dy = center[b * 3 + 1] - xyz[(b * KQ + k) * 3 + 1];
    float dz = center[b * 3 + 2] - xyz[(b * KQ + k) * 3 + 2];
    float dist = sqrtf(dx * dx + dy * dy + dz * dz);
    float d = om ? dist : INF;

    __shared__ float ds[KQ];
    ds[k] = d;
    __syncthreads();

    // bitonic sort ascending, 128 elems / 128 threads
    for (int sz = 2; sz <= KQ; sz <<= 1) {
        for (int j = sz >> 1; j > 0; j >>= 1) {
            int ixj = k ^ j;
            if (ixj > k) {
                bool up = ((k & sz) == 0);
                float a = ds[k], bb = ds[ixj];
                if ((a > bb) == up) { ds[k] = bb; ds[ixj] = a; }
            }
            __syncthreads();
        }
    }
    float maxd = ds[15];                      // 16th smallest (incl. inf pads)
    bool msk = om && (d <= maxd);
    g_mask[b * KQ + k] = msk ? 1 : 0;
    out_mask[b * KQ + k] = msk ? 1.f : 0.f;
}

// ------------------------- init kernel ---------------------------------------
// builds g_init = [mean_k enc, ref_obj] and prefills ref_obj segment of g_x
__global__ void init_kernel(const float* __restrict__ enc,
                            const float* __restrict__ ref_obj)
{
    int b = blockIdx.x, tid = threadIdx.x;  // 384 threads
    if (tid < VDQ) {
        float s = 0.f;
        const float* eb = enc + (size_t)b * KQ * VDQ;
        #pragma unroll 4
        for (int k = 0; k < KQ; k++) s += eb[k * VDQ + tid];
        g_init[b * (VDQ + ODQ) + tid] = s * (1.f / (float)KQ);
    } else {
        int j = tid - VDQ;                  // 0..255
        float v = ref_obj[b * ODQ + j];
        g_init[b * (VDQ + ODQ) + VDQ + j] = v;
        g_x[b * XDIM + EQ + VDQ + j] = v;   // constant across timesteps
    }
}

// ------------------------- generic tiled SGEMM (C = A * B^T + bias) ---------
// A: [M,K] row-major, B: [N,K] row-major. act: 0 none, 1 sigmoid.
// addC: accumulate into existing C. lang_len != null: zero row m if t >= lang_len[m].
template <int BM, int BN, int TM, int TN>
__global__ void sgemm_nt(const float* __restrict__ A, const float* __restrict__ B,
                         const float* __restrict__ bias, float* __restrict__ C,
                         int M, int N, int K, int act, int addC,
                         const int* __restrict__ lang_len, int t, int ldc)
{
    const int BK = 16;
    __shared__ float As[BM][BK + 1];
    __shared__ float Bs[BN][BK + 1];
    int tid = threadIdx.x;
    int m0 = blockIdx.y * BM, n0 = blockIdx.x * BN;
    const int TPX = BN / TN;
    int tx = tid % TPX, ty = tid / TPX;

    float acc[TM][TN];
    #pragma unroll
    for (int i = 0; i < TM; i++)
        #pragma unroll
        for (int j = 0; j < TN; j++) acc[i][j] = 0.f;

    for (int k0 = 0; k0 < K; k0 += BK) {
        for (int idx = tid; idx < BM * BK; idx += blockDim.x) {
            int r = idx / BK, cc = idx % BK;
            int mm = m0 + r, kk = k0 + cc;
            As[r][cc] = (mm < M && kk < K) ? A[(size_t)mm * K + kk] : 0.f;
        }
        for (int idx = tid; idx < BN * BK; idx += blockDim.x) {
            int r = idx / BK, cc = idx % BK;
            int nn = n0 + r, kk = k0 + cc;
            Bs[r][cc] = (nn < N && kk < K) ? B[(size_t)nn * K + kk] : 0.f;
        }
        __syncthreads();
        #pragma unroll
        for (int kk = 0; kk < BK; kk++) {
            float a[TM], bb[TN];
            #pragma unroll
            for (int i = 0; i < TM; i++) a[i] = As[ty * TM + i][kk];
            #pragma unroll
            for (int j = 0; j < TN; j++) bb[j] = Bs[tx * TN + j][kk];
            #pragma unroll
            for (int i = 0; i < TM; i++)
                #pragma unroll
                for (int j = 0; j < TN; j++) acc[i][j] += a[i] * bb[j];
        }
        __syncthreads();
    }

    #pragma unroll
    for (int i = 0; i < TM; i++) {
        int mm = m0 + ty * TM + i;
        if (mm >= M) continue;
        bool zero = (lang_len != nullptr) && (t >= lang_len[mm]);
        #pragma unroll
        for (int j = 0; j < TN; j++) {
            int nn = n0 + tx * TN + j;
            if (nn >= N) continue;
            float v = acc[i][j] + bias[nn];
            if (addC) v += C[(size_t)mm * ldc + nn];
            if (act == 1) v = sigf(v);
            if (zero) v = 0.f;
            C[(size_t)mm * ldc + nn] = v;
        }
    }
}

// ------------------------- fused attention step ------------------------------
// scores from att1+att2, masked softmax, gated awe -> g_x[:,300:428],
// embedding gather -> g_x[:,0:300], alpha -> out (masked by active)
__global__ void attention_step(const float* __restrict__ enc,
                               const float* __restrict__ w_full,
                               const float* __restrict__ b_full,
                               const float* __restrict__ emb_table,
                               const float* __restrict__ init_emb,
                               const int* __restrict__ lang_indices,
                               const int* __restrict__ lang_len,
                               float* __restrict__ out_alpha, int t)
{
    int b = blockIdx.x, tid = threadIdx.x;          // 512 threads
    int warp = tid >> 5, lane = tid & 31;

    __shared__ float att2_s[AQ];
    __shared__ float w_s[AQ];
    __shared__ float att_s[KQ];
    __shared__ float red[KQ];
    __shared__ float alpha_s[KQ];
    __shared__ float part[512];

    att2_s[tid] = g_att2[b * AQ + tid];
    w_s[tid] = w_full[tid];
    __syncthreads();

    // scores: 16 warps x 8 k-values each
    for (int k = warp; k < KQ; k += 16) {
        const float* a1 = g_att1 + ((size_t)b * KQ + k) * AQ;
        float s = 0.f;
        for (int a = lane; a < AQ; a += 32) {
            float v = a1[a] + att2_s[a];
            s += fmaxf(v, 0.f) * w_s[a];
        }
        #pragma unroll
        for (int o = 16; o; o >>= 1) s += __shfl_down_sync(0xffffffffu, s, o);
        if (lane == 0) att_s[k] = s + b_full[0];
    }
    __syncthreads();

    // masked softmax over K=128
    if (tid < KQ)
        red[tid] = g_mask[b * KQ + tid] ? att_s[tid] : -__int_as_float(0x7f800000);
    __syncthreads();
    for (int s = 64; s > 0; s >>= 1) {
        if (tid < s) red[tid] = fmaxf(red[tid], red[tid + s]);
        __syncthreads();
    }
    float mx = red[0];
    if (isinf(mx)) mx = 0.f;
    __syncthreads();
    if (tid < KQ) {
        float e = g_mask[b * KQ + tid] ? expf(att_s[tid] - mx) : 0.f;
        alpha_s[tid] = e;
        red[tid] = e;
    }
    __syncthreads();
    for (int s = 64; s > 0; s >>= 1) {
        if (tid < s) red[tid] += red[tid + s];
        __syncthreads();
    }
    float dsum = red[0];
    float inv = (dsum > 0.f) ? 1.f / fmaxf(dsum, 1e-30f) : 0.f;
    __syncthreads();
    if (tid < KQ) alpha_s[tid] *= inv;
    __syncthreads();

    // awe[v] = sum_k alpha[k]*enc[b,k,v] ; 4 partial groups over k
    {
        int v = tid & (VDQ - 1), q = tid >> 7;      // q in 0..3
        const float* eb = enc + (size_t)b * KQ * VDQ;
        float s = 0.f;
        for (int k = q * 32; k < q * 32 + 32; k++) s += alpha_s[k] * eb[k * VDQ + v];
        part[tid] = s;
    }
    __syncthreads();

    bool active = (t < lang_len[b]);
    if (tid < VDQ) {
        float aw = part[tid] + part[tid + 128] + part[tid + 256] + part[tid + 384];
        g_x[b * XDIM + EQ + tid] = aw * g_gate[b * VDQ + tid];
        out_alpha[(size_t)b * TQ * KQ + (size_t)t * KQ + tid] = active ? alpha_s[tid] : 0.f;
    }
    // embedding gather for this step: t==0 -> init_emb, else emb_table[idx[t-1]]
    if (tid < EQ) {
        float e;
        if (t == 0) e = init_emb[tid];
        else e = emb_table[(size_t)lang_indices[b * TQ + (t - 1)] * EQ + tid];
        g_x[b * XDIM + tid] = e;
    }
}

// ------------------------- LSTM cell update ----------------------------------
__global__ void lstm_update(const int* __restrict__ lang_len, int t)
{
    int b = blockIdx.x;
    int j = blockIdx.y * 256 + threadIdx.x;      // 0..511
    const float* gr = g_gates + (size_t)b * 4 * DQ;
    float gi = gr[j];
    float gf = gr[DQ + j];
    float gg = gr[2 * DQ + j];
    float go = gr[3 * DQ + j];
    float c_old = g_c[b * DQ + j];
    float cn = sigf(gf) * c_old + sigf(gi) * tanhf(gg);
    float hn = sigf(go) * tanhf(cn);
    if (t < lang_len[b]) {
        g_c[b * DQ + j] = cn;
        g_h[b * DQ + j] = hn;
    }
}

// ------------------------- final transpose [T,B,V] -> [B,V,T] ---------------
__global__ void transpose_preds(float* __restrict__ out)
{
    __shared__ float tile[32][33];
    int b = blockIdx.x;
    int v0 = blockIdx.y * 32;
    int tx = threadIdx.x, ty = threadIdx.y;
    // read: t = ty, v = v0+tx (coalesced in v)
    tile[ty][tx] = g_predsT[(size_t)ty * BQ * VQ + (size_t)b * VQ + v0 + tx];
    __syncthreads();
    // write: v = v0+ty, t = tx (coalesced in t)
    out[(size_t)b * VQ * TQ + (size_t)(v0 + ty) * TQ + tx] = tile[tx][ty];
}

// ------------------------- launch ---------------------------------------------
extern "C" void kernel_launch(void* const* d_in, const int* in_sizes, int n_in,
                              void* d_out, int out_size)
{
    const float* enc       = (const float*)d_in[0];
    const float* ref_obj   = (const float*)d_in[1];
    const float* obj_sc    = (const float*)d_in[2];
    const float* center    = (const float*)d_in[3];
    const float* xyz       = (const float*)d_in[4];
    const int*   lang_idx  = (const int*)d_in[5];
    const int*   lang_len  = (const int*)d_in[6];
    const float* emb_tab   = (const float*)d_in[7];
    const float* init_emb  = (const float*)d_in[8];
    const float* W_enc_att = (const float*)d_in[9];
    const float* b_enc_att = (const float*)d_in[10];
    const float* W_dec_att = (const float*)d_in[11];
    const float* b_dec_att = (const float*)d_in[12];
    const float* w_full    = (const float*)d_in[13];
    const float* b_full    = (const float*)d_in[14];
    const float* W_ih      = (const float*)d_in[15];
    const float* b_ih      = (const float*)d_in[16];
    const float* W_hh      = (const float*)d_in[17];
    const float* b_hh      = (const float*)d_in[18];
    const float* W_init_h  = (const float*)d_in[19];
    const float* b_init_h  = (const float*)d_in[20];
    const float* W_init_c  = (const float*)d_in[21];
    const float* b_init_c  = (const float*)d_in[22];
    const float* W_fbeta   = (const float*)d_in[23];
    const float* b_fbeta   = (const float*)d_in[24];
    const float* W_fc      = (const float*)d_in[25];
    const float* b_fc      = (const float*)d_in[26];

    float* out       = (float*)d_out;
    float* out_alpha = out + (size_t)BQ * VQ * TQ;
    float* out_mask  = out_alpha + (size_t)BQ * TQ * KQ;

    float *p_att1, *p_att2, *p_gate, *p_h, *p_c, *p_x, *p_gates, *p_init, *p_predsT;
    cudaGetSymbolAddress((void**)&p_att1,   g_att1);
    cudaGetSymbolAddress((void**)&p_att2,   g_att2);
    cudaGetSymbolAddress((void**)&p_gate,   g_gate);
    cudaGetSymbolAddress((void**)&p_h,      g_h);
    cudaGetSymbolAddress((void**)&p_c,      g_c);
    cudaGetSymbolAddress((void**)&p_x,      g_x);
    cudaGetSymbolAddress((void**)&p_gates,  g_gates);
    cudaGetSymbolAddress((void**)&p_init,   g_init);
    cudaGetSymbolAddress((void**)&p_predsT, g_predsT);

    // precompute
    mask_kernel<<<BQ, KQ>>>(obj_sc, center, xyz, out_mask);
    init_kernel<<<BQ, VDQ + ODQ>>>(enc, ref_obj);
    // h0, c0 : [128,512] = init_in[128,384] @ W^T
    sgemm_nt<32,32,2,2><<<dim3(16, 4), 256>>>(p_init, W_init_h, b_init_h, p_h,
                                              BQ, DQ, VDQ + ODQ, 0, 0, nullptr, 0, DQ);
    sgemm_nt<32,32,2,2><<<dim3(16, 4), 256>>>(p_init, W_init_c, b_init_c, p_c,
                                              BQ, DQ, VDQ + ODQ, 0, 0, nullptr, 0, DQ);
    // att1: [16384,512] = enc[16384,128] @ W_enc_att^T
    sgemm_nt<64,64,4,4><<<dim3(8, 256), 256>>>(enc, W_enc_att, b_enc_att, p_att1,
                                               BQ * KQ, AQ, VDQ, 0, 0, nullptr, 0, AQ);

    for (int t = 0; t < TQ; t++) {
        // att2 = h @ W_dec_att^T + b
        sgemm_nt<32,32,2,2><<<dim3(16, 4), 256>>>(p_h, W_dec_att, b_dec_att, p_att2,
                                                  BQ, AQ, DQ, 0, 0, nullptr, 0, AQ);
        // gate = sigmoid(h @ W_fbeta^T + b)
        sgemm_nt<32,32,2,2><<<dim3(4, 4), 256>>>(p_h, W_fbeta, b_fbeta, p_gate,
                                                 BQ, VDQ, DQ, 1, 0, nullptr, 0, VDQ);
        // attention + softmax + awe + x assembly
        attention_step<<<BQ, 512>>>(enc, w_full, b_full, emb_tab, init_emb,
                                    lang_idx, lang_len, out_alpha, t);
        // gates = x @ W_ih^T + b_ih  (then += h @ W_hh^T + b_hh)
        sgemm_nt<32,64,2,4><<<dim3(32, 4), 256>>>(p_x, W_ih, b_ih, p_gates,
                                                  BQ, 4 * DQ, XDIM, 0, 0, nullptr, 0, 4 * DQ);
        sgemm_nt<32,64,2,4><<<dim3(32, 4), 256>>>(p_h, W_hh, b_hh, p_gates,
                                                  BQ, 4 * DQ, DQ, 0, 1, nullptr, 0, 4 * DQ);
        // LSTM cell (masked update of h, c)
        lstm_update<<<dim3(BQ, 2), 256>>>(lang_len, t);
        // preds_t = h @ W_fc^T + b_fc (zeroed for inactive rows), into [t][b][v]
        sgemm_nt<64,64,4,4><<<dim3(63, 2), 256>>>(p_h, W_fc, b_fc,
                                                  p_predsT + (size_t)t * BQ * VQ,
                                                  BQ, VQ, DQ, 0, 0, lang_len, t, VQ);
    }

    // [T,B,V] -> [B,V,T]
    transpose_preds<<<dim3(BQ, VQ / 32), dim3(32, 32)>>>(out);
}

// round 2
// speedup vs baseline: 2.1073x; 2.1073x over previous
#include <cuda_runtime.h>
#include <math.h>
#include <stdint.h>

#define BQ 128
#define KQ 128
#define VDQ 128
#define ODQ 256
#define EQ 300
#define AQ 512
#define DQ 512
#define VQ 4000
#define TQ 32
#define XDIM 684     // E + VD + OD
#define YDIM 2688    // 512 (dec_att) + 128 (fbeta) + 2048 (hh)

// ------------------------- scratch (device globals) -------------------------
__device__ float g_att1[(size_t)BQ * KQ * AQ];        // 32 MB
__device__ float g_Y[BQ * YDIM];
__device__ float g_h[BQ * DQ];
__device__ float g_c[BQ * DQ];
__device__ float g_x[BQ * XDIM];
__device__ float g_init[BQ * (VDQ + ODQ)];
__device__ float g_hstore[(size_t)TQ * BQ * DQ];      // 8 MB, [t][b][j]
__device__ float g_predsT[(size_t)TQ * BQ * VQ];      // 64 MB, [t][b][v]
__device__ unsigned char g_mask[BQ * KQ];

typedef unsigned long long ull;
__device__ __forceinline__ ull pk2(float x, float y) {
    ull r; asm("mov.b64 %0,{%1,%2};" : "=l"(r) : "f"(x), "f"(y)); return r;
}
__device__ __forceinline__ void fma2(ull& d, ull a, ull b) {
    asm("fma.rn.f32x2 %0,%1,%2,%0;" : "+l"(d) : "l"(a), "l"(b));
}
__device__ __forceinline__ float lo32(ull v) { return __uint_as_float((unsigned)v); }
__device__ __forceinline__ float hi32(ull v) { return __uint_as_float((unsigned)(v >> 32)); }
__device__ __forceinline__ float sigf(float x) { return 1.f / (1.f + expf(-x)); }

// ------------------------- object mask kernel -------------------------------
__global__ void mask_kernel(const float* __restrict__ obj,
                            const float* __restrict__ center,
                            const float* __restrict__ xyz,
                            float* __restrict__ out_mask)
{
    int b = blockIdx.x, k = threadIdx.x;
    const float INF = __int_as_float(0x7f800000);

    float s0 = obj[(b * KQ + k) * 2];
    float s1 = obj[(b * KQ + k) * 2 + 1];
    float objn = 1.f / (1.f + expf(s0 - s1));
    bool om = objn > 0.75f;

    float dx = center[b * 3 + 0] - xyz[(b * KQ + k) * 3 + 0];
    float dy = center[b * 3 + 1] - xyz[(b * KQ + k) * 3 + 1];
    float dz = center[b * 3 + 2] - xyz[(b * KQ + k) * 3 + 2];
    float dist = sqrtf(dx * dx + dy * dy + dz * dz);
    float d = om ? dist : INF;

    __shared__ float ds[KQ];
    ds[k] = d;
    __syncthreads();
    for (int sz = 2; sz <= KQ; sz <<= 1) {
        for (int j = sz >> 1; j > 0; j >>= 1) {
            int ixj = k ^ j;
            if (ixj > k) {
                bool up = ((k & sz) == 0);
                float a = ds[k], bb = ds[ixj];
                if ((a > bb) == up) { ds[k] = bb; ds[ixj] = a; }
            }
            __syncthreads();
        }
    }
    float maxd = ds[15];
    bool msk = om && (d <= maxd);
    g_mask[b * KQ + k] = msk ? 1 : 0;
    out_mask[b * KQ + k] = msk ? 1.f : 0.f;
}

// ------------------------- init kernel ---------------------------------------
__global__ void init_kernel(const float* __restrict__ enc,
                            const float* __restrict__ ref_obj)
{
    int b = blockIdx.x, tid = threadIdx.x;  // 384 threads
    if (tid < VDQ) {
        float s = 0.f;
        const float* eb = enc + (size_t)b * KQ * VDQ;
        #pragma unroll 4
        for (int k = 0; k < KQ; k++) s += eb[k * VDQ + tid];
        g_init[b * (VDQ + ODQ) + tid] = s * (1.f / (float)KQ);
    } else {
        int j = tid - VDQ;
        float v = ref_obj[b * ODQ + j];
        g_init[b * (VDQ + ODQ) + VDQ + j] = v;
        g_x[b * XDIM + EQ + VDQ + j] = v;   // constant across timesteps
    }
}

// ------------------------- small generic SGEMM (h0/c0 only) -----------------
template <int BM, int BN, int TM, int TN>
__global__ void sgemm_nt(const float* __restrict__ A, const float* __restrict__ B,
                         const float* __restrict__ bias, float* __restrict__ C,
                         int M, int N, int K, int ldc)
{
    const int BK = 16;
    __shared__ float As[BM][BK + 1];
    __shared__ float Bs[BN][BK + 1];
    int tid = threadIdx.x;
    int m0 = blockIdx.y * BM, n0 = blockIdx.x * BN;
    const int TPX = BN / TN;
    int tx = tid % TPX, ty = tid / TPX;

    float acc[TM][TN];
    #pragma unroll
    for (int i = 0; i < TM; i++)
        #pragma unroll
        for (int j = 0; j < TN; j++) acc[i][j] = 0.f;

    for (int k0 = 0; k0 < K; k0 += BK) {
        for (int idx = tid; idx < BM * BK; idx += blockDim.x) {
            int r = idx / BK, cc = idx % BK;
            int mm = m0 + r, kk = k0 + cc;
            As[r][cc] = (mm < M && kk < K) ? A[(size_t)mm * K + kk] : 0.f;
        }
        for (int idx = tid; idx < BN * BK; idx += blockDim.x) {
            int r = idx / BK, cc = idx % BK;
            int nn = n0 + r, kk = k0 + cc;
            Bs[r][cc] = (nn < N && kk < K) ? B[(size_t)nn * K + kk] : 0.f;
        }
        __syncthreads();
        #pragma unroll
        for (int kk = 0; kk < BK; kk++) {
            float a[TM], bb[TN];
            #pragma unroll
            for (int i = 0; i < TM; i++) a[i] = As[ty * TM + i][kk];
            #pragma unroll
            for (int j = 0; j < TN; j++) bb[j] = Bs[tx * TN + j][kk];
            #pragma unroll
            for (int i = 0; i < TM; i++)
                #pragma unroll
                for (int j = 0; j < TN; j++) acc[i][j] += a[i] * bb[j];
        }
        __syncthreads();
    }
    #pragma unroll
    for (int i = 0; i < TM; i++) {
        int mm = m0 + ty * TM + i;
        if (mm >= M) continue;
        #pragma unroll
        for (int j = 0; j < TN; j++) {
            int nn = n0 + tx * TN + j;
            if (nn >= N) continue;
            C[(size_t)mm * ldc + nn] = acc[i][j] + bias[nn];
        }
    }
}

// ------------------------- h2y: Y = h @ [Wd;Wf;Whh]^T ------------------------
// BM=32, BN=64, BK=16, TM=2, TN=4, 256 threads, f32x2 accumulation
__global__ void h2y_kernel(const float* __restrict__ Wd, const float* __restrict__ Wf,
                           const float* __restrict__ Whh)
{
    const int BK = 16;
    __shared__ float As[BK][32];
    __shared__ float Bs[BK][64];
    int tid = threadIdx.x;
    int m0 = blockIdx.y * 32;
    int n0 = blockIdx.x * 64;
    const float* Bp; int boff;
    if (n0 < 512)      { Bp = Wd;  boff = n0; }
    else if (n0 < 640) { Bp = Wf;  boff = n0 - 512; }
    else               { Bp = Whh; boff = n0 - 640; }

    int tx = tid & 15, ty = tid >> 4;
    ull acc[2][2] = {{0ull, 0ull}, {0ull, 0ull}};

    for (int k0 = 0; k0 < DQ; k0 += BK) {
        if (tid < 128) {
            int m = tid >> 2, kq = (tid & 3) * 4;
            float4 v = *(const float4*)&g_h[(m0 + m) * DQ + k0 + kq];
            As[kq + 0][m] = v.x; As[kq + 1][m] = v.y; As[kq + 2][m] = v.z; As[kq + 3][m] = v.w;
        }
        {
            int n = tid >> 2, kq = (tid & 3) * 4;
            float4 v = *(const float4*)&Bp[(size_t)(boff + n) * DQ + k0 + kq];
            Bs[kq + 0][n] = v.x; Bs[kq + 1][n] = v.y; Bs[kq + 2][n] = v.z; Bs[kq + 3][n] = v.w;
        }
        __syncthreads();
        #pragma unroll
        for (int kk = 0; kk < BK; kk++) {
            float2 a = *(const float2*)&As[kk][ty * 2];
            ull a0 = pk2(a.x, a.x), a1 = pk2(a.y, a.y);
            const ull* bp = (const ull*)&Bs[kk][tx * 4];
            ull b01 = bp[0], b23 = bp[1];
            fma2(acc[0][0], a0, b01); fma2(acc[0][1], a0, b23);
            fma2(acc[1][0], a1, b01); fma2(acc[1][1], a1, b23);
        }
        __syncthreads();
    }
    #pragma unroll
    for (int i = 0; i < 2; i++) {
        int m = m0 + ty * 2 + i;
        float* cr = g_Y + m * YDIM + n0 + tx * 4;
        cr[0] = lo32(acc[i][0]); cr[1] = hi32(acc[i][0]);
        cr[2] = lo32(acc[i][1]); cr[3] = hi32(acc[i][1]);
    }
}

// ------------------------- fused attention step ------------------------------
__global__ void attention_step(const float* __restrict__ enc,
                               const float* __restrict__ b_dec,
                               const float* __restrict__ b_fbeta,
                               const float* __restrict__ w_full,
                               const float* __restrict__ b_full,
                               const float* __restrict__ emb_table,
                               const float* __restrict__ init_emb,
                               const int* __restrict__ lang_indices,
                               const int* __restrict__ lang_len,
                               float* __restrict__ out_alpha, int t)
{
    int b = blockIdx.x, tid = threadIdx.x;          // 512 threads
    int warp = tid >> 5, lane = tid & 31;

    __shared__ float att2_s[AQ];
    __shared__ float w_s[AQ];
    __shared__ float att_s[KQ];
    __shared__ float red[KQ];
    __shared__ float alpha_s[KQ];
    __shared__ float part[512];

    att2_s[tid] = g_Y[b * YDIM + tid] + b_dec[tid];
    w_s[tid] = w_full[tid];
    __syncthreads();

    for (int k = warp; k < KQ; k += 16) {
        const float* a1 = g_att1 + ((size_t)b * KQ + k) * AQ;
        float s = 0.f;
        #pragma unroll 4
        for (int a = lane; a < AQ; a += 32) {
            float v = a1[a] + att2_s[a];
            s += fmaxf(v, 0.f) * w_s[a];
        }
        #pragma unroll
        for (int o = 16; o; o >>= 1) s += __shfl_down_sync(0xffffffffu, s, o);
        if (lane == 0) att_s[k] = s + b_full[0];
    }
    __syncthreads();

    if (tid < KQ)
        red[tid] = g_mask[b * KQ + tid] ? att_s[tid] : -__int_as_float(0x7f800000);
    __syncthreads();
    for (int s = 64; s > 0; s >>= 1) {
        if (tid < s) red[tid] = fmaxf(red[tid], red[tid + s]);
        __syncthreads();
    }
    float mx = red[0];
    if (isinf(mx)) mx = 0.f;
    __syncthreads();
    if (tid < KQ) {
        float e = g_mask[b * KQ + tid] ? expf(att_s[tid] - mx) : 0.f;
        alpha_s[tid] = e;
        red[tid] = e;
    }
    __syncthreads();
    for (int s = 64; s > 0; s >>= 1) {
        if (tid < s) red[tid] += red[tid + s];
        __syncthreads();
    }
    float dsum = red[0];
    float inv = (dsum > 0.f) ? 1.f / fmaxf(dsum, 1e-30f) : 0.f;
    __syncthreads();
    if (tid < KQ) alpha_s[tid] *= inv;
    __syncthreads();

    {
        int v = tid & (VDQ - 1), q = tid >> 7;
        const float* eb = enc + (size_t)b * KQ * VDQ;
        float s = 0.f;
        #pragma unroll 4
        for (int k = q * 32; k < q * 32 + 32; k++) s += alpha_s[k] * eb[k * VDQ + v];
        part[tid] = s;
    }
    __syncthreads();

    bool active = (t < lang_len[b]);
    if (tid < VDQ) {
        float aw = part[tid] + part[tid + 128] + part[tid + 256] + part[tid + 384];
        float gate = sigf(g_Y[b * YDIM + 512 + tid] + b_fbeta[tid]);
        g_x[b * XDIM + EQ + tid] = aw * gate;
        out_alpha[(size_t)b * TQ * KQ + (size_t)t * KQ + tid] = active ? alpha_s[tid] : 0.f;
    }
    if (tid < EQ) {
        float e;
        if (t == 0) e = init_emb[tid];
        else e = emb_table[(size_t)lang_indices[b * TQ + (t - 1)] * EQ + tid];
        g_x[b * XDIM + tid] = e;
    }
}

// ------------------------- gates GEMM + LSTM fused ---------------------------
// Computes gates = x @ W_ih^T, adds b_ih + b_hh + Y_hh, does LSTM cell update.
// Block: 32 b-rows x 16 j-cols (x4 gate segments). 256 threads.
__global__ void gates_lstm(const float* __restrict__ Wih,
                           const float* __restrict__ b_ih,
                           const float* __restrict__ b_hh,
                           const int* __restrict__ lang_len, int t)
{
    const int BK = 16;
    __shared__ float As[BK][32];     // x tile
    __shared__ float Bs[BK][64];     // W_ih rows: seg*16 + j_local
    int tid = threadIdx.x;
    int j0 = blockIdx.x * 16;
    int m0 = blockIdx.y * 32;
    int tx = tid & 15, ty = tid >> 4;
    ull acc[4] = {0ull, 0ull, 0ull, 0ull};   // per gate segment, packed over (b0,b1)

    for (int k0 = 0; k0 < XDIM; k0 += BK) {
        if (tid < 128) {
            int m = tid >> 2, kq = (tid & 3) * 4;
            int k = k0 + kq;
            if (k + 4 <= XDIM) {
                float4 v = *(const float4*)&g_x[(m0 + m) * XDIM + k];
                As[kq + 0][m] = v.x; As[kq + 1][m] = v.y; As[kq + 2][m] = v.z; As[kq + 3][m] = v.w;
            } else {
                #pragma unroll
                for (int i = 0; i < 4; i++)
                    As[kq + i][m] = (k + i < XDIM) ? g_x[(m0 + m) * XDIM + k + i] : 0.f;
            }
        }
        {
            int r = tid >> 2, kq = (tid & 3) * 4;
            int seg = r >> 4, jl = r & 15;
            int row = seg * 512 + j0 + jl;
            int k = k0 + kq;
            if (k + 4 <= XDIM) {
                float4 v = *(const float4*)&Wih[(size_t)row * XDIM + k];
                Bs[kq + 0][r] = v.x; Bs[kq + 1][r] = v.y; Bs[kq + 2][r] = v.z; Bs[kq + 3][r] = v.w;
            } else {
                #pragma unroll
                for (int i = 0; i < 4; i++)
                    Bs[kq + i][r] = (k + i < XDIM) ? Wih[(size_t)row * XDIM + k + i] : 0.f;
            }
        }
        __syncthreads();
        #pragma unroll
        for (int kk = 0; kk < BK; kk++) {
            ull a01 = *(const ull*)&As[kk][ty * 2];   // (x[b0,k], x[b1,k])
            #pragma unroll
            for (int s = 0; s < 4; s++) {
                float bb = Bs[kk][s * 16 + tx];
                fma2(acc[s], a01, pk2(bb, bb));
            }
        }
        __syncthreads();
    }

    int j = j0 + tx;
    #pragma unroll
    for (int half = 0; half < 2; half++) {
        int b = m0 + ty * 2 + half;
        float gi = half ? hi32(acc[0]) : lo32(acc[0]);
        float gf = half ? hi32(acc[1]) : lo32(acc[1]);
        float gg = half ? hi32(acc[2]) : lo32(acc[2]);
        float go = half ? hi32(acc[3]) : lo32(acc[3]);
        const float* Yb = g_Y + b * YDIM + 640;
        gi += b_ih[j]          + b_hh[j]          + Yb[j];
        gf += b_ih[512 + j]    + b_hh[512 + j]    + Yb[512 + j];
        gg += b_ih[1024 + j]   + b_hh[1024 + j]   + Yb[1024 + j];
        go += b_ih[1536 + j]   + b_hh[1536 + j]   + Yb[1536 + j];
        float c_old = g_c[b * DQ + j];
        float cn = sigf(gf) * c_old + sigf(gi) * tanhf(gg);
        float hn = sigf(go) * tanhf(cn);
        bool act = t < lang_len[b];
        float h_out = act ? hn : g_h[b * DQ + j];
        if (act) { g_c[b * DQ + j] = cn; g_h[b * DQ + j] = hn; }
        g_hstore[((size_t)t * BQ + b) * DQ + j] = h_out;
    }
}

// ------------------------- big GEMM (att1, fc) --------------------------------
// C[M,N] = A[M,K] @ B[N,K]^T + bias. BM=64, BN=128, BK=16, TM=4, TN=8, 256 thr.
// If lang_len != null: zero output row m when (m>>7) >= lang_len[m&127].
__global__ void gemm_big(const float* __restrict__ A, const float* __restrict__ B,
                         const float* __restrict__ bias, float* __restrict__ C,
                         int M, int N, int K, int ldc,
                         const int* __restrict__ lang_len)
{
    const int BK = 16;
    __shared__ float As[BK][64];
    __shared__ float Bs[BK][128];
    int tid = threadIdx.x;
    int m0 = blockIdx.y * 64, n0 = blockIdx.x * 128;
    int tx = tid & 15, ty = tid >> 4;
    ull acc[4][4];
    #pragma unroll
    for (int i = 0; i < 4; i++)
        #pragma unroll
        for (int p = 0; p < 4; p++) acc[i][p] = 0ull;

    for (int k0 = 0; k0 < K; k0 += BK) {
        {
            int m = tid >> 2, kq = (tid & 3) * 4;
            float4 v = *(const float4*)&A[(size_t)(m0 + m) * K + k0 + kq];
            As[kq + 0][m] = v.x; As[kq + 1][m] = v.y; As[kq + 2][m] = v.z; As[kq + 3][m] = v.w;
        }
        #pragma unroll
        for (int rr = 0; rr < 2; rr++) {
            int r = tid + rr * 256;
            int n = r >> 2, kq = (r & 3) * 4;
            int nn = n0 + n;
            float4 v = make_float4(0.f, 0.f, 0.f, 0.f);
            if (nn < N) v = *(const float4*)&B[(size_t)nn * K + k0 + kq];
            Bs[kq + 0][n] = v.x; Bs[kq + 1][n] = v.y; Bs[kq + 2][n] = v.z; Bs[kq + 3][n] = v.w;
        }
        __syncthreads();
        #pragma unroll
        for (int kk = 0; kk < BK; kk++) {
            float4 av = *(const float4*)&As[kk][ty * 4];
            ull pa0 = pk2(av.x, av.x), pa1 = pk2(av.y, av.y);
            ull pa2 = pk2(av.z, av.z), pa3 = pk2(av.w, av.w);
            const ull* bp = (const ull*)&Bs[kk][tx * 8];
            ull b0 = bp[0], b1 = bp[1], b2 = bp[2], b3 = bp[3];
            fma2(acc[0][0], pa0, b0); fma2(acc[0][1], pa0, b1); fma2(acc[0][2], pa0, b2); fma2(acc[0][3], pa0, b3);
            fma2(acc[1][0], pa1, b0); fma2(acc[1][1], pa1, b1); fma2(acc[1][2], pa1, b2); fma2(acc[1][3], pa1, b3);
            fma2(acc[2][0], pa2, b0); fma2(acc[2][1], pa2, b1); fma2(acc[2][2], pa2, b2); fma2(acc[2][3], pa2, b3);
            fma2(acc[3][0], pa3, b0); fma2(acc[3][1], pa3, b1); fma2(acc[3][2], pa3, b2); fma2(acc[3][3], pa3, b3);
        }
        __syncthreads();
    }

    #pragma unroll
    for (int i = 0; i < 4; i++) {
        int m = m0 + ty * 4 + i;
        bool zero = (lang_len != nullptr) && ((m >> 7) >= lang_len[m & 127]);
        float* cr = C + (size_t)m * ldc;
        #pragma unroll
        for (int p = 0; p < 4; p++) {
            int nn = n0 + tx * 8 + p * 2;
            if (nn < N) {
                float v = lo32(acc[i][p]) + bias[nn];
                cr[nn] = zero ? 0.f : v;
            }
            if (nn + 1 < N) {
                float v = hi32(acc[i][p]) + bias[nn + 1];
                cr[nn + 1] = zero ? 0.f : v;
            }
        }
    }
}

// ------------------------- final transpose [T,B,V] -> [B,V,T] ----------------
__global__ void transpose_preds(float* __restrict__ out)
{
    __shared__ float tile[32][33];
    int b = blockIdx.x;
    int v0 = blockIdx.y * 32;
    int tx = threadIdx.x, ty = threadIdx.y;
    tile[ty][tx] = g_predsT[(size_t)ty * BQ * VQ + (size_t)b * VQ + v0 + tx];
    __syncthreads();
    out[(size_t)b * VQ * TQ + (size_t)(v0 + ty) * TQ + tx] = tile[tx][ty];
}

// ------------------------- launch ---------------------------------------------
extern "C" void kernel_launch(void* const* d_in, const int* in_sizes, int n_in,
                              void* d_out, int out_size)
{
    const float* enc       = (const float*)d_in[0];
    const float* ref_obj   = (const float*)d_in[1];
    const float* obj_sc    = (const float*)d_in[2];
    const float* center    = (const float*)d_in[3];
    const float* xyz       = (const float*)d_in[4];
    const int*   lang_idx  = (const int*)d_in[5];
    const int*   lang_len  = (const int*)d_in[6];
    const float* emb_tab   = (const float*)d_in[7];
    const float* init_emb  = (const float*)d_in[8];
    const float* W_enc_att = (const float*)d_in[9];
    const float* b_enc_att = (const float*)d_in[10];
    const float* W_dec_att = (const float*)d_in[11];
    const float* b_dec_att = (const float*)d_in[12];
    const float* w_full    = (const float*)d_in[13];
    const float* b_full    = (const float*)d_in[14];
    const float* W_ih      = (const float*)d_in[15];
    const float* b_ih      = (const float*)d_in[16];
    const float* W_hh      = (const float*)d_in[17];
    const float* b_hh      = (const float*)d_in[18];
    const float* W_init_h  = (const float*)d_in[19];
    const float* b_init_h  = (const float*)d_in[20];
    const float* W_init_c  = (const float*)d_in[21];
    const float* b_init_c  = (const float*)d_in[22];
    const float* W_fbeta   = (const float*)d_in[23];
    const float* b_fbeta   = (const float*)d_in[24];
    const float* W_fc      = (const float*)d_in[25];
    const float* b_fc      = (const float*)d_in[26];

    float* out       = (float*)d_out;
    float* out_alpha = out + (size_t)BQ * VQ * TQ;
    float* out_mask  = out_alpha + (size_t)BQ * TQ * KQ;

    float *p_att1, *p_h, *p_c, *p_init, *p_hstore, *p_predsT;
    cudaGetSymbolAddress((void**)&p_att1,   g_att1);
    cudaGetSymbolAddress((void**)&p_h,      g_h);
    cudaGetSymbolAddress((void**)&p_c,      g_c);
    cudaGetSymbolAddress((void**)&p_init,   g_init);
    cudaGetSymbolAddress((void**)&p_hstore, g_hstore);
    cudaGetSymbolAddress((void**)&p_predsT, g_predsT);

    // precompute
    mask_kernel<<<BQ, KQ>>>(obj_sc, center, xyz, out_mask);
    init_kernel<<<BQ, VDQ + ODQ>>>(enc, ref_obj);
    sgemm_nt<32,32,2,2><<<dim3(16, 4), 256>>>(p_init, W_init_h, b_init_h, p_h,
                                              BQ, DQ, VDQ + ODQ, DQ);
    sgemm_nt<32,32,2,2><<<dim3(16, 4), 256>>>(p_init, W_init_c, b_init_c, p_c,
                                              BQ, DQ, VDQ + ODQ, DQ);
    // att1: [16384,512] = enc[16384,128] @ W_enc_att^T
    gemm_big<<<dim3(4, 256), 256>>>(enc, W_enc_att, b_enc_att, p_att1,
                                    BQ * KQ, AQ, VDQ, AQ, nullptr);

    for (int t = 0; t < TQ; t++) {
        // Y = h @ [W_dec_att; W_fbeta; W_hh]^T  (no bias)
        h2y_kernel<<<dim3(YDIM / 64, BQ / 32), 256>>>(W_dec_att, W_fbeta, W_hh);
        // attention + softmax + gated awe + emb gather -> g_x
        attention_step<<<BQ, 512>>>(enc, b_dec_att, b_fbeta, w_full, b_full,
                                    emb_tab, init_emb, lang_idx, lang_len,
                                    out_alpha, t);
        // gates = x @ W_ih^T + (b_ih + b_hh + Y_hh), fused LSTM update
        gates_lstm<<<dim3(DQ / 16, BQ / 32), 256>>>(W_ih, b_ih, b_hh, lang_len, t);
    }

    // one big fc: preds[T*B, V] = hstore @ W_fc^T + b_fc (rows zeroed by lang_len)
    gemm_big<<<dim3((VQ + 127) / 128, (TQ * BQ) / 64), 256>>>(
        p_hstore, W_fc, b_fc, p_predsT, TQ * BQ, VQ, DQ, VQ, lang_len);

    // [T,B,V] -> [B,V,T]
    transpose_preds<<<dim3(BQ, VQ / 32), dim3(32, 32)>>>(out);
}